// round 12
// baseline (speedup 1.0000x reference)
#include <cuda_runtime.h>
#include <cuda_bf16.h>
#include <cstdint>

#define Tn 1024
#define Bn 8
#define En 1024
#define Hn 16
#define HDn 64
#define Mn (Tn*Bn)           // 8192 rows
#define SCALE_F 0.125f       // 64^-0.5

// tcgen05 only exists in the arch-specific (compute_103a) device pass.
#if defined(__CUDA_ARCH_FEAT_SM103_ALL) || (defined(__CUDA_ARCH_SPECIFIC__) && (__CUDA_ARCH_SPECIFIC__ == 1030))
#define USE_TCGEN05 1
#else
#define USE_TCGEN05 0
#endif

// ---------------- scratch (device globals = sanctioned workaround) ----------
__device__ float g_Q[(size_t)Mn * En];
__device__ float g_K[(size_t)Mn * En];
__device__ float g_V[(size_t)Mn * En];
__device__ __nv_bfloat16 g_Ahi[(size_t)Mn * En];
__device__ __nv_bfloat16 g_Alo[(size_t)Mn * En];
__device__ __nv_bfloat16 g_Whi[4][(size_t)En * En];   // transposed: [n][k]
__device__ __nv_bfloat16 g_Wlo[4][(size_t)En * En];

#define SWZ(o) ((o) ^ (((o) >> 3) & 0x70))

__device__ __forceinline__ uint32_t pack2(__nv_bfloat16 a, __nv_bfloat16 b) {
    __nv_bfloat162 t(a, b);
    return *reinterpret_cast<uint32_t*>(&t);
}

#if USE_TCGEN05
// ---------------- PTX helpers (sm_103a pass only) ----------------------------
__device__ __forceinline__ uint32_t smem_u32(const void* p) {
    uint32_t r;
    asm("{ .reg .u64 t; cvta.to.shared.u64 t, %1; cvt.u32.u64 %0, t; }" : "=r"(r) : "l"(p));
    return r;
}
__device__ __forceinline__ uint32_t elect1() {
    uint32_t p;
    asm volatile("{ .reg .pred p; elect.sync _|p, 0xFFFFFFFF; selp.b32 %0, 1, 0, p; }" : "=r"(p));
    return p;
}
static __device__ __forceinline__ uint64_t make_desc(uint32_t addr) {
    // SW128, version=1 (Blackwell), SBO=64 (1024B row-group), LBO=1 (16B)
    const uint64_t base = (2ULL << 61) | (1ULL << 46) | (64ULL << 32) | (1ULL << 16);
    return base | ((uint64_t)(addr >> 4) & 0x3FFF);
}
// c=F32, a=BF16, b=BF16, K-major both, M=128
#define IDESC_N128 0x8200490u
#define IDESC_N64  0x8100490u

__device__ __forceinline__ void mma_f16_ss(uint32_t d, uint64_t a_desc, uint64_t b_desc,
                                           uint32_t idesc, uint32_t en) {
    asm volatile(
        "{\n\t.reg .pred p;\n\tsetp.ne.u32 p, %4, 0;\n\t"
        "tcgen05.mma.cta_group::1.kind::f16 [%0], %1, %2, %3, {%5, %5, %5, %5}, p;\n\t}"
        :: "r"(d), "l"(a_desc), "l"(b_desc), "r"(idesc), "r"(en), "r"(0u) : "memory");
}
__device__ __forceinline__ void tmem_alloc(uint32_t smem_dst, uint32_t ncols) {
    asm volatile("tcgen05.alloc.cta_group::1.sync.aligned.shared::cta.b32 [%0], %1;"
                 :: "r"(smem_dst), "r"(ncols) : "memory");
}
__device__ __forceinline__ void tmem_dealloc(uint32_t tmem, uint32_t ncols) {
    asm volatile("tcgen05.dealloc.cta_group::1.sync.aligned.b32 %0, %1;" :: "r"(tmem), "r"(ncols));
}
__device__ __forceinline__ void tmem_relinquish() {
    asm volatile("tcgen05.relinquish_alloc_permit.cta_group::1.sync.aligned;");
}
__device__ __forceinline__ void tc_commit(uint32_t mbar) {
    asm volatile("tcgen05.commit.cta_group::1.mbarrier::arrive::one.shared::cluster.b64 [%0];"
                 :: "r"(mbar) : "memory");
}
__device__ __forceinline__ void mbar_init(uint32_t mbar, uint32_t cnt) {
    asm volatile("mbarrier.init.shared.b64 [%0], %1;" :: "r"(mbar), "r"(cnt) : "memory");
}
__device__ __forceinline__ void mbar_inval(uint32_t mbar) {
    asm volatile("mbarrier.inval.shared.b64 [%0];" :: "r"(mbar) : "memory");
}
__device__ __forceinline__ void mbar_wait(uint32_t mbar, uint32_t parity) {
    asm volatile(
        "{\n\t.reg .pred P1;\n\t"
        "WAIT_LOOP_%=:\n\t"
        "mbarrier.try_wait.parity.acquire.cta.shared::cta.b64 P1, [%0], %1, 0x989680;\n\t"
        "@P1 bra.uni WAIT_DONE_%=;\n\t"
        "bra.uni WAIT_LOOP_%=;\n\t"
        "WAIT_DONE_%=:\n\t}"
        :: "r"(mbar), "r"(parity) : "memory");
}
__device__ __forceinline__ void ldtm_x32(uint32_t* r, uint32_t tmem_addr) {
    asm volatile(
        "tcgen05.ld.sync.aligned.32x32b.x32.b32 "
        "{%0, %1, %2, %3, %4, %5, %6, %7, %8, %9, %10, %11, %12, %13, %14, %15, "
        " %16, %17, %18, %19, %20, %21, %22, %23, %24, %25, %26, %27, %28, %29, %30, %31}, [%32];"
        : "=r"(r[0]), "=r"(r[1]), "=r"(r[2]), "=r"(r[3]), "=r"(r[4]), "=r"(r[5]), "=r"(r[6]), "=r"(r[7]),
          "=r"(r[8]), "=r"(r[9]), "=r"(r[10]), "=r"(r[11]), "=r"(r[12]), "=r"(r[13]), "=r"(r[14]), "=r"(r[15]),
          "=r"(r[16]), "=r"(r[17]), "=r"(r[18]), "=r"(r[19]), "=r"(r[20]), "=r"(r[21]), "=r"(r[22]), "=r"(r[23]),
          "=r"(r[24]), "=r"(r[25]), "=r"(r[26]), "=r"(r[27]), "=r"(r[28]), "=r"(r[29]), "=r"(r[30]), "=r"(r[31])
        : "r"(tmem_addr));
}
__device__ __forceinline__ void tc_wait_ld()      { asm volatile("tcgen05.wait::ld.sync.aligned;" ::: "memory"); }
__device__ __forceinline__ void tc_fence_after()  { asm volatile("tcgen05.fence::after_thread_sync;" ::: "memory"); }
__device__ __forceinline__ void tc_fence_before() { asm volatile("tcgen05.fence::before_thread_sync;" ::: "memory"); }
#endif  // USE_TCGEN05

// ---------------- split-convert: fp32 -> bf16 hi/lo --------------------------
__global__ void __launch_bounds__(256) convert_split(const float* __restrict__ in) {
    const size_t i = ((size_t)blockIdx.x * 256 + threadIdx.x) * 4;
    float4 v = *(const float4*)(in + i);
    __nv_bfloat16 h0 = __float2bfloat16(v.x), h1 = __float2bfloat16(v.y);
    __nv_bfloat16 h2 = __float2bfloat16(v.z), h3 = __float2bfloat16(v.w);
    __nv_bfloat16 l0 = __float2bfloat16(v.x - __bfloat162float(h0));
    __nv_bfloat16 l1 = __float2bfloat16(v.y - __bfloat162float(h1));
    __nv_bfloat16 l2 = __float2bfloat16(v.z - __bfloat162float(h2));
    __nv_bfloat16 l3 = __float2bfloat16(v.w - __bfloat162float(h3));
    uint2 hv; hv.x = pack2(h0, h1); hv.y = pack2(h2, h3);
    uint2 lv; lv.x = pack2(l0, l1); lv.y = pack2(l2, l3);
    *(uint2*)(g_Ahi + i) = hv;
    *(uint2*)(g_Alo + i) = lv;
}

// weights: transpose + split.  Wt[n][k] = split(W[k][n])
__global__ void __launch_bounds__(256) convert_w(const float* __restrict__ w0,
                                                 const float* __restrict__ w1,
                                                 const float* __restrict__ w2,
                                                 const float* __restrict__ w3) {
    __shared__ float tile[32][33];
    const int z = blockIdx.z;
    const float* W = (z == 0) ? w0 : (z == 1) ? w1 : (z == 2) ? w2 : w3;
    const int tx = threadIdx.x & 31;
    const int ty = threadIdx.x >> 5;
    const int n0 = blockIdx.x * 32, k0 = blockIdx.y * 32;
#pragma unroll
    for (int i = 0; i < 4; i++)
        tile[ty + i * 8][tx] = W[(size_t)(k0 + ty + i * 8) * En + n0 + tx];
    __syncthreads();
#pragma unroll
    for (int i = 0; i < 4; i++) {
        const float v = tile[tx][ty + i * 8];
        const int n = n0 + ty + i * 8, k = k0 + tx;
        __nv_bfloat16 h = __float2bfloat16(v);
        __nv_bfloat16 l = __float2bfloat16(v - __bfloat162float(h));
        g_Whi[z][(size_t)n * En + k] = h;
        g_Wlo[z][(size_t)n * En + k] = l;
    }
}

__device__ __forceinline__ void unpack4(uint2 h, uint2 l, float* f) {
    __nv_bfloat162 h0 = *reinterpret_cast<__nv_bfloat162*>(&h.x);
    __nv_bfloat162 h1 = *reinterpret_cast<__nv_bfloat162*>(&h.y);
    __nv_bfloat162 l0 = *reinterpret_cast<__nv_bfloat162*>(&l.x);
    __nv_bfloat162 l1 = *reinterpret_cast<__nv_bfloat162*>(&l.y);
    f[0] = __bfloat162float(h0.x) + __bfloat162float(l0.x);
    f[1] = __bfloat162float(h0.y) + __bfloat162float(l0.y);
    f[2] = __bfloat162float(h1.x) + __bfloat162float(l1.x);
    f[3] = __bfloat162float(h1.y) + __bfloat162float(l1.y);
}

__device__ __forceinline__ void split_pack8(float4 a, float4 b, uint4& H, uint4& L) {
    float f[8] = {a.x, a.y, a.z, a.w, b.x, b.y, b.z, b.w};
    uint32_t hh[4], ll[4];
#pragma unroll
    for (int i = 0; i < 4; i++) {
        __nv_bfloat16 h0 = __float2bfloat16(f[2 * i]);
        __nv_bfloat16 h1 = __float2bfloat16(f[2 * i + 1]);
        hh[i] = pack2(h0, h1);
        ll[i] = pack2(__float2bfloat16(f[2 * i] - __bfloat162float(h0)),
                      __float2bfloat16(f[2 * i + 1] - __bfloat162float(h1)));
    }
    H = make_uint4(hh[0], hh[1], hh[2], hh[3]);
    L = make_uint4(ll[0], ll[1], ll[2], ll[3]);
}

// ---------------- GEMM v3: C[128,128] tile, K=1024, 2 CTAs/SM ----------------
// Half-row ping-pong: the single 64KB SW128 buffer's 128-B rows hold two
// independent K=32 sub-chunks (bytes 0-63 and 64-127). Fill half h of sub s
// while the MMA on half h^1 (sub s-1) runs — intra-CTA load/MMA overlap with
// no extra SMEM, same descriptors (offsets {0,2} / {4,6} units), and still
// 2 CTAs/SM for cross-CTA overlap.
#define BGEMM_SMEM (1024 + 65536)

__global__ void __launch_bounds__(256, 2) bgemm(int mode, float* __restrict__ Cout) {
    extern __shared__ char smem[];
    const int tid = threadIdx.x;
    const int bm = blockIdx.y * 128, bn = blockIdx.x * 128;
    const int z = blockIdx.z;
    const int widx = (mode == 0) ? z : 3;

    const __nv_bfloat16* __restrict__ Ah = g_Ahi;
    const __nv_bfloat16* __restrict__ Al = g_Alo;
    const __nv_bfloat16* __restrict__ Wh = g_Whi[widx];
    const __nv_bfloat16* __restrict__ Wl = g_Wlo[widx];

#if USE_TCGEN05
    const uint32_t sb = smem_u32(smem);
    const int wid = tid >> 5, lid = tid & 31;

    if (wid == 0) { tmem_alloc(sb + 0, 128); tmem_relinquish(); }
    if (tid == 0) { mbar_init(sb + 8, 1); mbar_init(sb + 16, 1); }
    __syncthreads();
    uint32_t tmem;
    asm volatile("ld.shared.b32 %0, [%1];" : "=r"(tmem) : "r"(sb + 0));

    const uint32_t bufo = 1024;
    const uint64_t dAh = make_desc(sb + bufo);
    const uint64_t dAl = make_desc(sb + bufo + 16384);
    const uint64_t dBh = make_desc(sb + bufo + 32768);
    const uint64_t dBl = make_desc(sb + bufo + 49152);

    uint32_t ph[2] = {0u, 0u};
    for (int sub = 0; sub < 32; ++sub) {
        const int half = sub & 1;
        if (sub >= 2) { mbar_wait(sb + 8 + half * 8, ph[half]); ph[half] ^= 1u; }
        const int k0 = sub * 32;
        // fill half-rows: each array 128 rows x 64 B = 512 uint4; 2/thread
#pragma unroll
        for (int t = 0; t < 2; ++t) {
            const int s  = tid + t * 256;          // 0..511
            const int r  = s >> 2;                 // 0..127
            const int c8 = (s & 3) << 3;           // 0,8,16,24
            const uint32_t so = SWZ((uint32_t)(r * 128 + half * 64 + c8 * 2));
            const size_t gi = (size_t)(bm + r) * En + k0 + c8;
            const size_t gw = (size_t)(bn + r) * En + k0 + c8;
            *(uint4*)(smem + bufo + so)         = *(const uint4*)(Ah + gi);
            *(uint4*)(smem + bufo + 16384 + so) = *(const uint4*)(Al + gi);
            *(uint4*)(smem + bufo + 32768 + so) = *(const uint4*)(Wh + gw);
            *(uint4*)(smem + bufo + 49152 + so) = *(const uint4*)(Wl + gw);
        }
        __syncthreads();
        if (wid == 0 && elect1()) {
            asm volatile("fence.proxy.async.shared::cta;" ::: "memory");
            const uint64_t off = (uint64_t)(half * 4);
#pragma unroll
            for (int ks = 0; ks < 2; ++ks)
                mma_f16_ss(tmem, dAh + off + ks * 2, dBh + off + ks * 2, IDESC_N128,
                           (sub > 0 || ks > 0) ? 1u : 0u);
#pragma unroll
            for (int ks = 0; ks < 2; ++ks)
                mma_f16_ss(tmem, dAh + off + ks * 2, dBl + off + ks * 2, IDESC_N128, 1u);
#pragma unroll
            for (int ks = 0; ks < 2; ++ks)
                mma_f16_ss(tmem, dAl + off + ks * 2, dBh + off + ks * 2, IDESC_N128, 1u);
            tc_commit(sb + 8 + half * 8);
        }
    }
    // last commit was sub=31 (half=1); it covers all prior MMAs
    mbar_wait(sb + 16, ph[1]);
    tc_fence_after();

    if (wid < 4) {
        const float scale = (mode == 0 && z == 0) ? SCALE_F : 1.f;
        float* C = mode ? Cout : (z == 0 ? g_Q : (z == 1 ? g_K : g_V));
        const int m = bm + wid * 32 + lid;
#pragma unroll 1
        for (int pass = 0; pass < 4; ++pass) {
            uint32_t r[32];
            ldtm_x32(r, tmem + pass * 32);
            tc_wait_ld();
            tc_fence_before();
            const int cbase = bn + pass * 32;
            float* p;
            if (mode) {
                p = C + (size_t)m * En + cbase;
            } else {
                const int t = m >> 3, b = m & 7;
                const int h = cbase >> 6, d0 = cbase & 63;
                p = C + ((size_t)(b * Hn + h) * Tn + t) * HDn + d0;
            }
#pragma unroll
            for (int j = 0; j < 8; ++j) {
                float4 v;
                v.x = __uint_as_float(r[j * 4 + 0]) * scale;
                v.y = __uint_as_float(r[j * 4 + 1]) * scale;
                v.z = __uint_as_float(r[j * 4 + 2]) * scale;
                v.w = __uint_as_float(r[j * 4 + 3]) * scale;
                *(float4*)(p + j * 4) = v;
            }
        }
    }
    __syncthreads();
    if (wid == 0) {
        if (elect1()) { mbar_inval(sb + 8); mbar_inval(sb + 16); }
        tmem_dealloc(tmem, 128);
    }
#else
    // FFMA fallback (never selected on sm_103a; keeps non-a pass compilable)
    float (*As)[128] = (float (*)[128])smem;
    float (*Bs)[128] = (float (*)[128])(smem + 8 * 128 * 4);
    const int row = tid >> 1, kq = (tid & 1) * 4;
    const int ty = tid >> 4, tx = tid & 15;
    float acc[8][8];
#pragma unroll
    for (int i = 0; i < 8; i++)
#pragma unroll
        for (int j = 0; j < 8; j++) acc[i][j] = 0.f;
    for (int k0 = 0; k0 < En; k0 += 8) {
        float fa[4], fb[4];
        const size_t gi = (size_t)(bm + row) * En + k0 + kq;
        unpack4(*(const uint2*)(Ah + gi), *(const uint2*)(Al + gi), fa);
        const size_t gw = (size_t)(bn + row) * En + k0 + kq;
        unpack4(*(const uint2*)(Wh + gw), *(const uint2*)(Wl + gw), fb);
#pragma unroll
        for (int i = 0; i < 4; i++) { As[kq + i][row] = fa[i]; Bs[kq + i][row] = fb[i]; }
        __syncthreads();
#pragma unroll
        for (int k = 0; k < 8; k++) {
            float ar[8], br[8];
            *(float4*)&ar[0] = *(const float4*)&As[k][ty * 8];
            *(float4*)&ar[4] = *(const float4*)&As[k][ty * 8 + 4];
            *(float4*)&br[0] = *(const float4*)&Bs[k][tx * 8];
            *(float4*)&br[4] = *(const float4*)&Bs[k][tx * 8 + 4];
#pragma unroll
            for (int i = 0; i < 8; i++)
#pragma unroll
                for (int j = 0; j < 8; j++) acc[i][j] = fmaf(ar[i], br[j], acc[i][j]);
        }
        __syncthreads();
    }
    const float scale = (mode == 0 && z == 0) ? SCALE_F : 1.f;
    float* C = mode ? Cout : (z == 0 ? g_Q : (z == 1 ? g_K : g_V));
#pragma unroll
    for (int i = 0; i < 8; i++) {
        const int m = bm + ty * 8 + i;
#pragma unroll
        for (int jb = 0; jb < 2; jb++) {
            const int col = bn + tx * 8 + jb * 4;
            float4 v;
            v.x = acc[i][jb * 4 + 0] * scale;
            v.y = acc[i][jb * 4 + 1] * scale;
            v.z = acc[i][jb * 4 + 2] * scale;
            v.w = acc[i][jb * 4 + 3] * scale;
            if (mode) *(float4*)(C + (size_t)m * En + col) = v;
            else {
                const int t = m >> 3, b = m & 7;
                const int h = col >> 6, d = col & 63;
                *(float4*)(C + ((size_t)(b * Hn + h) * Tn + t) * HDn + d) = v;
            }
        }
    }
#endif
}

// ---------------------------------------------------------------------------
// Tensor-core flash attention, v3.1 (unchanged from round 11): 64-key tiles,
// 2 CTAs/SM via immediate alloc-permit relinquish.
//
// SMEM map (bytes, total 100352 = 98KB -> 2 CTAs/SM):
//   0 tmem ptr | 8 mb0 | 16 mb1 | 32 mk[64] | 288 rs[256]
//   1536   bias_s (128 rows x 32 words bf16x2 = 16384)
//   18432  Qhi(16K)  34816 Qlo(16K)
//   51200  Khi(8K)   59392 Klo(8K)     [P-hi aliases 51200..67584, 16K]
//   67584  Vthi(8K)  75776 Vtlo(8K)
//   83968  Plo(16K)  -> end 100352
// TMEM: S cols 0-63 (fp32), O cols 64-127 (fp32). alloc 128 (2 CTAs = 256).
// ---------------------------------------------------------------------------
#define AOFF_MK    32
#define AOFF_RS    288
#define AOFF_BIAS  1536
#define AOFF_QHI   18432
#define AOFF_QLO   34816
#define AOFF_KHI   51200
#define AOFF_KLO   59392
#define AOFF_PHI   AOFF_KHI
#define AOFF_VTHI  67584
#define AOFF_VTLO  75776
#define AOFF_PLO   83968
#define ATT_SMEM   100352

__global__ void __launch_bounds__(256, 2) tc_attn(const float* __restrict__ bias,
                                                  const unsigned int* __restrict__ mask)
{
    extern __shared__ char smem[];
    const int tid = threadIdx.x;
    const int qt = blockIdx.x;    // 0..7
    const int bh = blockIdx.y;    // 0..127
    const int b = bh >> 4, h = bh & 15;

#if USE_TCGEN05
    const uint32_t sb = smem_u32(smem);
    const int wid = tid >> 5, lane = tid & 31;
    const int half = wid >> 2;                 // 0..1 (col half of the 64 keys)
    const int row  = (wid & 3) * 32 + lane;    // 0..127 local q row
    float* mk = (float*)(smem + AOFF_MK);
    float* rs = (float*)(smem + AOFF_RS);
    const float NEG_INF = __int_as_float(0xff800000);

    // Alloc TMEM and IMMEDIATELY relinquish the alloc permit so the second
    // co-resident CTA on this SM can run its own tcgen05.alloc.
    if (wid == 0) { tmem_alloc(sb + 0, 128); tmem_relinquish(); }
    if (tid == 0) { mbar_init(sb + 8, 1); mbar_init(sb + 16, 1); }

    // Q tile fill (fp32 -> bf16 hi/lo, SW128 K-major 128x64)
    const float* Qbase = g_Q + ((size_t)bh * Tn + qt * 128) * HDn;
#pragma unroll
    for (int t = 0; t < 4; ++t) {
        const int s = tid + t * 256;
        const int r = s >> 3, c8 = (s & 7) << 3;
        const float* src = Qbase + (size_t)r * HDn + c8;
        uint4 H, L;
        split_pack8(*(const float4*)src, *(const float4*)(src + 4), H, L);
        const uint32_t so = SWZ(r * 128 + c8 * 2);
        *(uint4*)(smem + AOFF_QHI + so) = H;
        *(uint4*)(smem + AOFF_QLO + so) = L;
    }
    __syncthreads();
    uint32_t tmem;
    asm volatile("ld.shared.b32 %0, [%1];" : "=r"(tmem) : "r"(sb + 0));

    const float* biasTile = bias + ((size_t)h * Tn + qt * 128) * Tn;
    float rowsum = 0.f;

    for (int kt = 0; kt < 16; ++kt) {
        if (kt > 0) mbar_wait(sb + 16, (kt - 1) & 1);   // PV(kt-1) done: K/P/Vt free
        // ---- fill K (64x64, hi/lo) ----
        const float* Kbase = g_K + ((size_t)bh * Tn + kt * 64) * HDn;
        const float* Vbase = g_V + ((size_t)bh * Tn + kt * 64) * HDn;
#pragma unroll
        for (int t = 0; t < 2; ++t) {
            const int s = tid + t * 256;        // 0..511
            const int r = s >> 3, c8 = (s & 7) << 3;
            const float* src = Kbase + (size_t)r * HDn + c8;
            uint4 H, L;
            split_pack8(*(const float4*)src, *(const float4*)(src + 4), H, L);
            const uint32_t so = SWZ(r * 128 + c8 * 2);
            *(uint4*)(smem + AOFF_KHI + so) = H;
            *(uint4*)(smem + AOFF_KLO + so) = L;
        }
        // ---- fill Vt (transposed 64d x 64keys, paired-key 4B stores) ----
#pragma unroll
        for (int it = 0; it < 2; ++it) {
            const int u = tid + it * 256;       // 0..511
            const int kp = u & 31;              // key pair -> keys 2kp, 2kp+1
            const int dg = u >> 5;              // 0..15 -> d = dg*4..dg*4+3
            const int key0 = kp * 2;
            const float4 va = *(const float4*)(Vbase + (size_t)key0 * HDn + dg * 4);
            const float4 vb = *(const float4*)(Vbase + (size_t)(key0 + 1) * HDn + dg * 4);
            const float fa[4] = {va.x, va.y, va.z, va.w};
            const float fb[4] = {vb.x, vb.y, vb.z, vb.w};
#pragma unroll
            for (int dd = 0; dd < 4; ++dd) {
                const int d = dg * 4 + dd;
                const __nv_bfloat16 ha = __float2bfloat16(fa[dd]);
                const __nv_bfloat16 hb = __float2bfloat16(fb[dd]);
                const __nv_bfloat16 la = __float2bfloat16(fa[dd] - __bfloat162float(ha));
                const __nv_bfloat16 lb = __float2bfloat16(fb[dd] - __bfloat162float(hb));
                const uint32_t so = SWZ((uint32_t)(d * 128 + key0 * 2));
                *(uint32_t*)(smem + AOFF_VTHI + so) = pack2(ha, hb);
                *(uint32_t*)(smem + AOFF_VTLO + so) = pack2(la, lb);
            }
        }
        if (tid < 64)
            mk[tid] = (mask[b * Tn + kt * 64 + tid] != 0u) ? NEG_INF : 0.f;
        __syncthreads();

        // ---- S = QK^T (3-term split), into TMEM cols 0-63 ----
        if (wid == 0 && elect1()) {
            asm volatile("fence.proxy.async.shared::cta;" ::: "memory");
            const uint64_t dQh = make_desc(sb + AOFF_QHI);
            const uint64_t dQl = make_desc(sb + AOFF_QLO);
            const uint64_t dKh = make_desc(sb + AOFF_KHI);
            const uint64_t dKl = make_desc(sb + AOFF_KLO);
#pragma unroll
            for (int ks = 0; ks < 4; ++ks)
                mma_f16_ss(tmem, dQh + ks * 2, dKh + ks * 2, IDESC_N64, ks > 0 ? 1u : 0u);
#pragma unroll
            for (int ks = 0; ks < 4; ++ks)
                mma_f16_ss(tmem, dQh + ks * 2, dKl + ks * 2, IDESC_N64, 1u);
#pragma unroll
            for (int ks = 0; ks < 4; ++ks)
                mma_f16_ss(tmem, dQl + ks * 2, dKh + ks * 2, IDESC_N64, 1u);
            tc_commit(sb + 8);
        }

        // ---- stage bias+mask tile into SMEM as bf16 (overlaps S MMA) ----
        // layout: 32 words/row (128B), word w stored at w ^ (row & 31)
        {
            const float* bsrc = biasTile + kt * 64;
#pragma unroll
            for (int t = 0; t < 8; ++t) {
                const int f = tid + t * 256;        // 0..2047
                const int r = f >> 4;               // 0..127
                const int cq = (f & 15) * 4;        // 0..60
                float4 v = *(const float4*)(bsrc + (size_t)r * Tn + cq);
                v.x += mk[cq];     v.y += mk[cq + 1];
                v.z += mk[cq + 2]; v.w += mk[cq + 3];
                const uint32_t w0 = pack2(__float2bfloat16(v.x), __float2bfloat16(v.y));
                const uint32_t w1 = pack2(__float2bfloat16(v.z), __float2bfloat16(v.w));
                uint32_t* bs = (uint32_t*)(smem + AOFF_BIAS + r * 128);
                const int wb = cq >> 1;
                bs[wb ^ (r & 31)]       = w0;
                bs[(wb + 1) ^ (r & 31)] = w1;
            }
        }
        __syncthreads();

        mbar_wait(sb + 8, kt & 1);   // S done: K region free -> P-hi writable
        tc_fence_after();

        // ---- softmax numerator: p = exp(S + bias_s); split to bf16 ----
        {
            const uint32_t* brow = (const uint32_t*)(smem + AOFF_BIAS + row * 128);
            uint32_t r[32];
            ldtm_x32(r, tmem + half * 32);
            tc_wait_ld();
            const int c0 = half * 32;
#pragma unroll
            for (int j = 0; j < 32; j += 2) {
                const uint32_t bw = brow[((c0 + j) >> 1) ^ (row & 31)];
                const __nv_bfloat162 bb = *reinterpret_cast<const __nv_bfloat162*>(&bw);
                const float s0 = __uint_as_float(r[j])     + __bfloat162float(bb.x);
                const float s1 = __uint_as_float(r[j + 1]) + __bfloat162float(bb.y);
                const float p0 = __expf(s0);
                const float p1 = __expf(s1);
                rowsum += p0 + p1;
                const __nv_bfloat16 h0 = __float2bfloat16(p0);
                const __nv_bfloat16 h1 = __float2bfloat16(p1);
                const __nv_bfloat16 l0 = __float2bfloat16(p0 - __bfloat162float(h0));
                const __nv_bfloat16 l1 = __float2bfloat16(p1 - __bfloat162float(h1));
                const uint32_t so = SWZ((uint32_t)(row * 128 + (c0 + j) * 2));
                *(uint32_t*)(smem + AOFF_PHI + so) = pack2(h0, h1);
                *(uint32_t*)(smem + AOFF_PLO + so) = pack2(l0, l1);
            }
        }
        __syncthreads();

        // ---- O += P V (3-term split), into TMEM cols 64-127 ----
        if (wid == 0 && elect1()) {
            asm volatile("fence.proxy.async.shared::cta;" ::: "memory");
            const uint64_t dPh = make_desc(sb + AOFF_PHI);
            const uint64_t dPl = make_desc(sb + AOFF_PLO);
            const uint64_t dVh = make_desc(sb + AOFF_VTHI);
            const uint64_t dVl = make_desc(sb + AOFF_VTLO);
#pragma unroll
            for (int ks = 0; ks < 4; ++ks)
                mma_f16_ss(tmem + 64, dPh + ks * 2, dVh + ks * 2, IDESC_N64,
                           (kt == 0 && ks == 0) ? 0u : 1u);
#pragma unroll
            for (int ks = 0; ks < 4; ++ks)
                mma_f16_ss(tmem + 64, dPh + ks * 2, dVl + ks * 2, IDESC_N64, 1u);
#pragma unroll
            for (int ks = 0; ks < 4; ++ks)
                mma_f16_ss(tmem + 64, dPl + ks * 2, dVh + ks * 2, IDESC_N64, 1u);
            tc_commit(sb + 16);
        }
    }
    mbar_wait(sb + 16, 15 & 1);
    tc_fence_after();

    // ---- epilogue: rowsum combine, O/rowsum, fused hi/lo split -> g_Ahi/lo --
    rs[half * 128 + row] = rowsum;
    __syncthreads();
    const float inv = 1.f / (rs[row] + rs[128 + row]);
    {
        uint32_t r[32];
        ldtm_x32(r, tmem + 64 + half * 32);
        tc_wait_ld();
        tc_fence_before();
        const int q_global = qt * 128 + row;
        const size_t base = ((size_t)q_global * Bn + b) * En + h * HDn + half * 32;
#pragma unroll
        for (int j = 0; j < 8; ++j) {
            float f[4];
            f[0] = __uint_as_float(r[j * 4 + 0]) * inv;
            f[1] = __uint_as_float(r[j * 4 + 1]) * inv;
            f[2] = __uint_as_float(r[j * 4 + 2]) * inv;
            f[3] = __uint_as_float(r[j * 4 + 3]) * inv;
            uint2 hv, lv;
#pragma unroll
            for (int i = 0; i < 2; ++i) {
                const __nv_bfloat16 h0 = __float2bfloat16(f[2 * i]);
                const __nv_bfloat16 h1 = __float2bfloat16(f[2 * i + 1]);
                ((uint32_t*)&hv)[i] = pack2(h0, h1);
                ((uint32_t*)&lv)[i] = pack2(
                    __float2bfloat16(f[2 * i]     - __bfloat162float(h0)),
                    __float2bfloat16(f[2 * i + 1] - __bfloat162float(h1)));
            }
            *(uint2*)(g_Ahi + base + j * 4) = hv;
            *(uint2*)(g_Alo + base + j * 4) = lv;
        }
    }
    __syncthreads();
    if (wid == 0) {
        if (elect1()) { mbar_inval(sb + 8); mbar_inval(sb + 16); }
        tmem_dealloc(tmem, 128);
    }
#else
    // FFMA fallback (never selected on sm_103a). One thread per q row.
    if (tid < 128) {
        const int q = qt * 128 + tid;
        const float* Qr = g_Q + ((size_t)bh * Tn + q) * HDn;
        float qv[64];
#pragma unroll
        for (int d = 0; d < 64; ++d) qv[d] = Qr[d];
        float o[64];
#pragma unroll
        for (int d = 0; d < 64; ++d) o[d] = 0.f;
        float sum = 0.f;
        const float* bp = bias + ((size_t)h * Tn + q) * Tn;
        for (int key = 0; key < Tn; ++key) {
            float s = bp[key];
            if (mask[b * Tn + key] != 0u) continue;
            const float* Kr = g_K + ((size_t)bh * Tn + key) * HDn;
            for (int d = 0; d < 64; ++d) s = fmaf(qv[d], Kr[d], s);
            const float p = __expf(s);
            sum += p;
            const float* Vr = g_V + ((size_t)bh * Tn + key) * HDn;
            for (int d = 0; d < 64; ++d) o[d] = fmaf(p, Vr[d], o[d]);
        }
        const float inv = 1.f / sum;
        const size_t base = ((size_t)q * Bn + b) * En + h * HDn;
        for (int d = 0; d < 64; ++d) {
            const float v = o[d] * inv;
            const __nv_bfloat16 hi = __float2bfloat16(v);
            g_Ahi[base + d] = hi;
            g_Alo[base + d] = __float2bfloat16(v - __bfloat162float(hi));
        }
    }
#endif
}

// ---------------------------------------------------------------------------
extern "C" void kernel_launch(void* const* d_in, const int* in_sizes, int n_in,
                              void* d_out, int out_size)
{
    (void)in_sizes; (void)n_in; (void)out_size;
    const float*        query = (const float*)d_in[0];
    const unsigned int* mask  = (const unsigned int*)d_in[1];
    const float*        bias  = (const float*)d_in[2];
    const float*        wq    = (const float*)d_in[3];
    const float*        wk    = (const float*)d_in[4];
    const float*        wv    = (const float*)d_in[5];
    const float*        wo    = (const float*)d_in[6];
    float*              out   = (float*)d_out;

    cudaFuncSetAttribute(bgemm, cudaFuncAttributeMaxDynamicSharedMemorySize, BGEMM_SMEM);
    cudaFuncSetAttribute(tc_attn, cudaFuncAttributeMaxDynamicSharedMemorySize, ATT_SMEM);

    // split inputs + weights
    convert_split<<<(Mn * En / 4) / 256, 256>>>(query);
    convert_w<<<dim3(32, 32, 4), 256>>>(wq, wk, wv, wo);

    // QKV projections (tensor cores; 2 CTAs/SM; half-row ping-pong)
    bgemm<<<dim3(8, 64, 3), 256, BGEMM_SMEM>>>(0, nullptr);

    // attention (tensor cores; 2 CTAs/SM; writes split output directly)
    tc_attn<<<dim3(8, 128), 256, ATT_SMEM>>>(bias, mask);

    // output projection
    bgemm<<<dim3(8, 64, 1), 256, BGEMM_SMEM>>>(1, out);
}

// round 14
// speedup vs baseline: 1.2945x; 1.2945x over previous
#include <cuda_runtime.h>
#include <cuda_bf16.h>
#include <cstdint>

#define Tn 1024
#define Bn 8
#define En 1024
#define Hn 16
#define HDn 64
#define Mn (Tn*Bn)           // 8192 rows
#define SCALE_F 0.125f       // 64^-0.5

// tcgen05 only exists in the arch-specific (compute_103a) device pass.
#if defined(__CUDA_ARCH_FEAT_SM103_ALL) || (defined(__CUDA_ARCH_SPECIFIC__) && (__CUDA_ARCH_SPECIFIC__ == 1030))
#define USE_TCGEN05 1
#else
#define USE_TCGEN05 0
#endif

// ---------------- scratch (device globals = sanctioned workaround) ----------
__device__ float g_Q[(size_t)Mn * En];
__device__ float g_K[(size_t)Mn * En];
__device__ float g_V[(size_t)Mn * En];
__device__ __nv_bfloat16 g_Ahi[(size_t)Mn * En];
__device__ __nv_bfloat16 g_Alo[(size_t)Mn * En];
__device__ __nv_bfloat16 g_Whi[4][(size_t)En * En];   // transposed: [n][k]
__device__ __nv_bfloat16 g_Wlo[4][(size_t)En * En];

#define SWZ(o) ((o) ^ (((o) >> 3) & 0x70))

__device__ __forceinline__ uint32_t pack2(__nv_bfloat16 a, __nv_bfloat16 b) {
    __nv_bfloat162 t(a, b);
    return *reinterpret_cast<uint32_t*>(&t);
}

#if USE_TCGEN05
// ---------------- PTX helpers (sm_103a pass only) ----------------------------
__device__ __forceinline__ uint32_t smem_u32(const void* p) {
    uint32_t r;
    asm("{ .reg .u64 t; cvta.to.shared.u64 t, %1; cvt.u32.u64 %0, t; }" : "=r"(r) : "l"(p));
    return r;
}
__device__ __forceinline__ uint32_t elect1() {
    uint32_t p;
    asm volatile("{ .reg .pred p; elect.sync _|p, 0xFFFFFFFF; selp.b32 %0, 1, 0, p; }" : "=r"(p));
    return p;
}
static __device__ __forceinline__ uint64_t make_desc(uint32_t addr) {
    // SW128, version=1 (Blackwell), SBO=64 (1024B row-group), LBO=1 (16B)
    const uint64_t base = (2ULL << 61) | (1ULL << 46) | (64ULL << 32) | (1ULL << 16);
    return base | ((uint64_t)(addr >> 4) & 0x3FFF);
}
// c=F32, a=BF16, b=BF16, K-major both, M=128
#define IDESC_N128 0x8200490u
#define IDESC_N64  0x8100490u

__device__ __forceinline__ void mma_f16_ss(uint32_t d, uint64_t a_desc, uint64_t b_desc,
                                           uint32_t idesc, uint32_t en) {
    asm volatile(
        "{\n\t.reg .pred p;\n\tsetp.ne.u32 p, %4, 0;\n\t"
        "tcgen05.mma.cta_group::1.kind::f16 [%0], %1, %2, %3, {%5, %5, %5, %5}, p;\n\t}"
        :: "r"(d), "l"(a_desc), "l"(b_desc), "r"(idesc), "r"(en), "r"(0u) : "memory");
}
__device__ __forceinline__ void tmem_alloc(uint32_t smem_dst, uint32_t ncols) {
    asm volatile("tcgen05.alloc.cta_group::1.sync.aligned.shared::cta.b32 [%0], %1;"
                 :: "r"(smem_dst), "r"(ncols) : "memory");
}
__device__ __forceinline__ void tmem_dealloc(uint32_t tmem, uint32_t ncols) {
    asm volatile("tcgen05.dealloc.cta_group::1.sync.aligned.b32 %0, %1;" :: "r"(tmem), "r"(ncols));
}
__device__ __forceinline__ void tmem_relinquish() {
    asm volatile("tcgen05.relinquish_alloc_permit.cta_group::1.sync.aligned;");
}
__device__ __forceinline__ void tc_commit(uint32_t mbar) {
    asm volatile("tcgen05.commit.cta_group::1.mbarrier::arrive::one.shared::cluster.b64 [%0];"
                 :: "r"(mbar) : "memory");
}
__device__ __forceinline__ void mbar_init(uint32_t mbar, uint32_t cnt) {
    asm volatile("mbarrier.init.shared.b64 [%0], %1;" :: "r"(mbar), "r"(cnt) : "memory");
}
__device__ __forceinline__ void mbar_inval(uint32_t mbar) {
    asm volatile("mbarrier.inval.shared.b64 [%0];" :: "r"(mbar) : "memory");
}
__device__ __forceinline__ void mbar_wait(uint32_t mbar, uint32_t parity) {
    asm volatile(
        "{\n\t.reg .pred P1;\n\t"
        "WAIT_LOOP_%=:\n\t"
        "mbarrier.try_wait.parity.acquire.cta.shared::cta.b64 P1, [%0], %1, 0x989680;\n\t"
        "@P1 bra.uni WAIT_DONE_%=;\n\t"
        "bra.uni WAIT_LOOP_%=;\n\t"
        "WAIT_DONE_%=:\n\t}"
        :: "r"(mbar), "r"(parity) : "memory");
}
__device__ __forceinline__ void ldtm_x32(uint32_t* r, uint32_t tmem_addr) {
    asm volatile(
        "tcgen05.ld.sync.aligned.32x32b.x32.b32 "
        "{%0, %1, %2, %3, %4, %5, %6, %7, %8, %9, %10, %11, %12, %13, %14, %15, "
        " %16, %17, %18, %19, %20, %21, %22, %23, %24, %25, %26, %27, %28, %29, %30, %31}, [%32];"
        : "=r"(r[0]), "=r"(r[1]), "=r"(r[2]), "=r"(r[3]), "=r"(r[4]), "=r"(r[5]), "=r"(r[6]), "=r"(r[7]),
          "=r"(r[8]), "=r"(r[9]), "=r"(r[10]), "=r"(r[11]), "=r"(r[12]), "=r"(r[13]), "=r"(r[14]), "=r"(r[15]),
          "=r"(r[16]), "=r"(r[17]), "=r"(r[18]), "=r"(r[19]), "=r"(r[20]), "=r"(r[21]), "=r"(r[22]), "=r"(r[23]),
          "=r"(r[24]), "=r"(r[25]), "=r"(r[26]), "=r"(r[27]), "=r"(r[28]), "=r"(r[29]), "=r"(r[30]), "=r"(r[31])
        : "r"(tmem_addr));
}
__device__ __forceinline__ void tc_wait_ld()      { asm volatile("tcgen05.wait::ld.sync.aligned;" ::: "memory"); }
__device__ __forceinline__ void tc_fence_after()  { asm volatile("tcgen05.fence::after_thread_sync;" ::: "memory"); }
__device__ __forceinline__ void tc_fence_before() { asm volatile("tcgen05.fence::before_thread_sync;" ::: "memory"); }
#endif  // USE_TCGEN05

// ---------------- split-convert: fp32 -> bf16 hi/lo --------------------------
__global__ void __launch_bounds__(256) convert_split(const float* __restrict__ in) {
    const size_t i = ((size_t)blockIdx.x * 256 + threadIdx.x) * 4;
    float4 v = *(const float4*)(in + i);
    __nv_bfloat16 h0 = __float2bfloat16(v.x), h1 = __float2bfloat16(v.y);
    __nv_bfloat16 h2 = __float2bfloat16(v.z), h3 = __float2bfloat16(v.w);
    __nv_bfloat16 l0 = __float2bfloat16(v.x - __bfloat162float(h0));
    __nv_bfloat16 l1 = __float2bfloat16(v.y - __bfloat162float(h1));
    __nv_bfloat16 l2 = __float2bfloat16(v.z - __bfloat162float(h2));
    __nv_bfloat16 l3 = __float2bfloat16(v.w - __bfloat162float(h3));
    uint2 hv; hv.x = pack2(h0, h1); hv.y = pack2(h2, h3);
    uint2 lv; lv.x = pack2(l0, l1); lv.y = pack2(l2, l3);
    *(uint2*)(g_Ahi + i) = hv;
    *(uint2*)(g_Alo + i) = lv;
}

// weights: transpose + split.  Wt[n][k] = split(W[k][n])
__global__ void __launch_bounds__(256) convert_w(const float* __restrict__ w0,
                                                 const float* __restrict__ w1,
                                                 const float* __restrict__ w2,
                                                 const float* __restrict__ w3) {
    __shared__ float tile[32][33];
    const int z = blockIdx.z;
    const float* W = (z == 0) ? w0 : (z == 1) ? w1 : (z == 2) ? w2 : w3;
    const int tx = threadIdx.x & 31;
    const int ty = threadIdx.x >> 5;
    const int n0 = blockIdx.x * 32, k0 = blockIdx.y * 32;
#pragma unroll
    for (int i = 0; i < 4; i++)
        tile[ty + i * 8][tx] = W[(size_t)(k0 + ty + i * 8) * En + n0 + tx];
    __syncthreads();
#pragma unroll
    for (int i = 0; i < 4; i++) {
        const float v = tile[tx][ty + i * 8];
        const int n = n0 + ty + i * 8, k = k0 + tx;
        __nv_bfloat16 h = __float2bfloat16(v);
        __nv_bfloat16 l = __float2bfloat16(v - __bfloat162float(h));
        g_Whi[z][(size_t)n * En + k] = h;
        g_Wlo[z][(size_t)n * En + k] = l;
    }
}

__device__ __forceinline__ void unpack4(uint2 h, uint2 l, float* f) {
    __nv_bfloat162 h0 = *reinterpret_cast<__nv_bfloat162*>(&h.x);
    __nv_bfloat162 h1 = *reinterpret_cast<__nv_bfloat162*>(&h.y);
    __nv_bfloat162 l0 = *reinterpret_cast<__nv_bfloat162*>(&l.x);
    __nv_bfloat162 l1 = *reinterpret_cast<__nv_bfloat162*>(&l.y);
    f[0] = __bfloat162float(h0.x) + __bfloat162float(l0.x);
    f[1] = __bfloat162float(h0.y) + __bfloat162float(l0.y);
    f[2] = __bfloat162float(h1.x) + __bfloat162float(l1.x);
    f[3] = __bfloat162float(h1.y) + __bfloat162float(l1.y);
}

__device__ __forceinline__ void split_pack8(float4 a, float4 b, uint4& H, uint4& L) {
    float f[8] = {a.x, a.y, a.z, a.w, b.x, b.y, b.z, b.w};
    uint32_t hh[4], ll[4];
#pragma unroll
    for (int i = 0; i < 4; i++) {
        __nv_bfloat16 h0 = __float2bfloat16(f[2 * i]);
        __nv_bfloat16 h1 = __float2bfloat16(f[2 * i + 1]);
        hh[i] = pack2(h0, h1);
        ll[i] = pack2(__float2bfloat16(f[2 * i] - __bfloat162float(h0)),
                      __float2bfloat16(f[2 * i + 1] - __bfloat162float(h1)));
    }
    H = make_uint4(hh[0], hh[1], hh[2], hh[3]);
    L = make_uint4(ll[0], ll[1], ll[2], ll[3]);
}

// ---------------- GEMM v4: C[128,256] tile, K=1024, 2 CTAs/SM ----------------
// Wider N halves the A-tile global traffic and the wave count (QKV 1536->768
// CTAs) while doubling MMA work per sync. SMEM: A 32K + W 64K + 1K = 97.3K ->
// still 2 CTAs/SM. TMEM 256 cols/CTA (2 CTAs = 512, exact fit). W rows
// 128-255 use a second descriptor at +16KB (swizzle is per-16K-half).
#define BGEMM_SMEM (1024 + 98304)

__global__ void __launch_bounds__(256, 2) bgemm(int mode, float* __restrict__ Cout) {
    extern __shared__ char smem[];
    const int tid = threadIdx.x;
    const int bm = blockIdx.y * 128, bn = blockIdx.x * 256;
    const int z = blockIdx.z;
    const int widx = (mode == 0) ? z : 3;

    const __nv_bfloat16* __restrict__ Ah = g_Ahi;
    const __nv_bfloat16* __restrict__ Al = g_Alo;
    const __nv_bfloat16* __restrict__ Wh = g_Whi[widx];
    const __nv_bfloat16* __restrict__ Wl = g_Wlo[widx];

#if USE_TCGEN05
    const uint32_t sb = smem_u32(smem);
    const int wid = tid >> 5, lid = tid & 31;

    if (wid == 0) { tmem_alloc(sb + 0, 256); tmem_relinquish(); }
    if (tid == 0) { mbar_init(sb + 8, 1); }
    __syncthreads();
    uint32_t tmem;
    asm volatile("ld.shared.b32 %0, [%1];" : "=r"(tmem) : "r"(sb + 0));

    const uint32_t oAh = 1024;
    const uint32_t oAl = 1024 + 16384;
    const uint32_t oWh = 1024 + 32768;          // 32K (256 rows)
    const uint32_t oWl = 1024 + 65536;          // 32K

    for (int c = 0; c < 16; ++c) {
        if (c > 0) mbar_wait(sb + 8, (c - 1) & 1);   // MMA(c-1) done: buffer free
        const int k0 = c * 64;
        // A tiles: 128 rows x 128B (hi+lo), 4 uint4/thread each
#pragma unroll
        for (int t = 0; t < 4; ++t) {
            const int s  = tid + t * 256;       // 0..1023
            const int r  = s >> 3;
            const int c8 = (s & 7) << 3;
            const uint32_t so = SWZ((uint32_t)(r * 128 + c8 * 2));
            const size_t gi = (size_t)(bm + r) * En + k0 + c8;
            *(uint4*)(smem + oAh + so) = *(const uint4*)(Ah + gi);
            *(uint4*)(smem + oAl + so) = *(const uint4*)(Al + gi);
        }
        // W tiles: 256 rows x 128B (hi+lo), 8 uint4/thread each
#pragma unroll
        for (int t = 0; t < 8; ++t) {
            const int s  = tid + t * 256;       // 0..2047
            const int r  = s >> 3;              // 0..255
            const int c8 = (s & 7) << 3;
            const uint32_t so = SWZ((uint32_t)(r * 128 + c8 * 2));
            const size_t gw = (size_t)(bn + r) * En + k0 + c8;
            *(uint4*)(smem + oWh + so) = *(const uint4*)(Wh + gw);
            *(uint4*)(smem + oWl + so) = *(const uint4*)(Wl + gw);
        }
        __syncthreads();
        if (wid == 0 && elect1()) {
            asm volatile("fence.proxy.async.shared::cta;" ::: "memory");
            const uint64_t dAh = make_desc(sb + oAh);
            const uint64_t dAl = make_desc(sb + oAl);
#pragma unroll
            for (int n = 0; n < 2; ++n) {
                const uint64_t dBh = make_desc(sb + oWh + n * 16384);
                const uint64_t dBl = make_desc(sb + oWl + n * 16384);
                const uint32_t d = tmem + n * 128;
#pragma unroll
                for (int ks = 0; ks < 4; ++ks)
                    mma_f16_ss(d, dAh + ks * 2, dBh + ks * 2, IDESC_N128,
                               (c > 0 || ks > 0) ? 1u : 0u);
#pragma unroll
                for (int ks = 0; ks < 4; ++ks)
                    mma_f16_ss(d, dAh + ks * 2, dBl + ks * 2, IDESC_N128, 1u);
#pragma unroll
                for (int ks = 0; ks < 4; ++ks)
                    mma_f16_ss(d, dAl + ks * 2, dBh + ks * 2, IDESC_N128, 1u);
            }
            tc_commit(sb + 8);
        }
    }
    mbar_wait(sb + 8, 15 & 1);
    tc_fence_after();

    if (wid < 4) {
        const float scale = (mode == 0 && z == 0) ? SCALE_F : 1.f;
        float* C = mode ? Cout : (z == 0 ? g_Q : (z == 1 ? g_K : g_V));
        const int m = bm + wid * 32 + lid;
#pragma unroll 1
        for (int pass = 0; pass < 8; ++pass) {
            uint32_t r[32];
            ldtm_x32(r, tmem + pass * 32);
            tc_wait_ld();
            tc_fence_before();
            const int cbase = bn + pass * 32;
            float* p;
            if (mode) {
                p = C + (size_t)m * En + cbase;
            } else {
                const int t = m >> 3, b = m & 7;
                const int h = cbase >> 6, d0 = cbase & 63;
                p = C + ((size_t)(b * Hn + h) * Tn + t) * HDn + d0;
            }
#pragma unroll
            for (int j = 0; j < 8; ++j) {
                float4 v;
                v.x = __uint_as_float(r[j * 4 + 0]) * scale;
                v.y = __uint_as_float(r[j * 4 + 1]) * scale;
                v.z = __uint_as_float(r[j * 4 + 2]) * scale;
                v.w = __uint_as_float(r[j * 4 + 3]) * scale;
                *(float4*)(p + j * 4) = v;
            }
        }
    }
    __syncthreads();
    if (wid == 0) {
        if (elect1()) { mbar_inval(sb + 8); }
        tmem_dealloc(tmem, 256);
    }
#else
    // FFMA fallback (never selected on sm_103a; keeps non-a pass compilable)
    float (*As)[128] = (float (*)[128])smem;
    float (*Bs)[128] = (float (*)[128])(smem + 8 * 128 * 4);
    const int row = tid >> 1, kq = (tid & 1) * 4;
    const int ty = tid >> 4, tx = tid & 15;
    // fallback computes the 128x256 tile as two 128x128 halves sequentially
    for (int nh = 0; nh < 2; ++nh) {
        const int bn2 = bn + nh * 128;
        float acc[8][8];
#pragma unroll
        for (int i = 0; i < 8; i++)
#pragma unroll
            for (int j = 0; j < 8; j++) acc[i][j] = 0.f;
        for (int k0 = 0; k0 < En; k0 += 8) {
            float fa[4], fb[4];
            const size_t gi = (size_t)(bm + row) * En + k0 + kq;
            unpack4(*(const uint2*)(Ah + gi), *(const uint2*)(Al + gi), fa);
            const size_t gw = (size_t)(bn2 + row) * En + k0 + kq;
            unpack4(*(const uint2*)(Wh + gw), *(const uint2*)(Wl + gw), fb);
#pragma unroll
            for (int i = 0; i < 4; i++) { As[kq + i][row] = fa[i]; Bs[kq + i][row] = fb[i]; }
            __syncthreads();
#pragma unroll
            for (int k = 0; k < 8; k++) {
                float ar[8], br[8];
                *(float4*)&ar[0] = *(const float4*)&As[k][ty * 8];
                *(float4*)&ar[4] = *(const float4*)&As[k][ty * 8 + 4];
                *(float4*)&br[0] = *(const float4*)&Bs[k][tx * 8];
                *(float4*)&br[4] = *(const float4*)&Bs[k][tx * 8 + 4];
#pragma unroll
                for (int i = 0; i < 8; i++)
#pragma unroll
                    for (int j = 0; j < 8; j++) acc[i][j] = fmaf(ar[i], br[j], acc[i][j]);
            }
            __syncthreads();
        }
        const float scale = (mode == 0 && z == 0) ? SCALE_F : 1.f;
        float* C = mode ? Cout : (z == 0 ? g_Q : (z == 1 ? g_K : g_V));
#pragma unroll
        for (int i = 0; i < 8; i++) {
            const int m = bm + ty * 8 + i;
#pragma unroll
            for (int jb = 0; jb < 2; jb++) {
                const int col = bn2 + tx * 8 + jb * 4;
                float4 v;
                v.x = acc[i][jb * 4 + 0] * scale;
                v.y = acc[i][jb * 4 + 1] * scale;
                v.z = acc[i][jb * 4 + 2] * scale;
                v.w = acc[i][jb * 4 + 3] * scale;
                if (mode) *(float4*)(C + (size_t)m * En + col) = v;
                else {
                    const int t = m >> 3, b = m & 7;
                    const int h = col >> 6, d = col & 63;
                    *(float4*)(C + ((size_t)(b * Hn + h) * Tn + t) * HDn + d) = v;
                }
            }
        }
        __syncthreads();
    }
#endif
}

// ---------------------------------------------------------------------------
// Tensor-core flash attention, v3.1 (round-11 version, REVERTED from v4):
// 64-key tiles, 2 CTAs/SM, full 3-term PV split — the PV lo-terms are
// REQUIRED: O is itself an average, so dropped 2^-9 terms do not shrink
// relative to it (round-13 failure at 2.2e-3).
//
// SMEM map (bytes, total 100352 = 98KB -> 2 CTAs/SM):
//   0 tmem ptr | 8 mb0 | 16 mb1 | 32 mk[64] | 288 rs[256]
//   1536   bias_s (128 rows x 32 words bf16x2 = 16384)
//   18432  Qhi(16K)  34816 Qlo(16K)
//   51200  Khi(8K)   59392 Klo(8K)     [P-hi aliases 51200..67584, 16K]
//   67584  Vthi(8K)  75776 Vtlo(8K)
//   83968  Plo(16K)  -> end 100352
// TMEM: S cols 0-63 (fp32), O cols 64-127 (fp32). alloc 128 (2 CTAs = 256).
// ---------------------------------------------------------------------------
#define AOFF_MK    32
#define AOFF_RS    288
#define AOFF_BIAS  1536
#define AOFF_QHI   18432
#define AOFF_QLO   34816
#define AOFF_KHI   51200
#define AOFF_KLO   59392
#define AOFF_PHI   AOFF_KHI
#define AOFF_VTHI  67584
#define AOFF_VTLO  75776
#define AOFF_PLO   83968
#define ATT_SMEM   100352

__global__ void __launch_bounds__(256, 2) tc_attn(const float* __restrict__ bias,
                                                  const unsigned int* __restrict__ mask)
{
    extern __shared__ char smem[];
    const int tid = threadIdx.x;
    const int qt = blockIdx.x;    // 0..7
    const int bh = blockIdx.y;    // 0..127
    const int b = bh >> 4, h = bh & 15;

#if USE_TCGEN05
    const uint32_t sb = smem_u32(smem);
    const int wid = tid >> 5, lane = tid & 31;
    const int half = wid >> 2;                 // 0..1 (col half of the 64 keys)
    const int row  = (wid & 3) * 32 + lane;    // 0..127 local q row
    float* mk = (float*)(smem + AOFF_MK);
    float* rs = (float*)(smem + AOFF_RS);
    const float NEG_INF = __int_as_float(0xff800000);

    // Alloc TMEM and IMMEDIATELY relinquish the alloc permit (co-residency).
    if (wid == 0) { tmem_alloc(sb + 0, 128); tmem_relinquish(); }
    if (tid == 0) { mbar_init(sb + 8, 1); mbar_init(sb + 16, 1); }

    // Q tile fill (fp32 -> bf16 hi/lo, SW128 K-major 128x64)
    const float* Qbase = g_Q + ((size_t)bh * Tn + qt * 128) * HDn;
#pragma unroll
    for (int t = 0; t < 4; ++t) {
        const int s = tid + t * 256;
        const int r = s >> 3, c8 = (s & 7) << 3;
        const float* src = Qbase + (size_t)r * HDn + c8;
        uint4 H, L;
        split_pack8(*(const float4*)src, *(const float4*)(src + 4), H, L);
        const uint32_t so = SWZ(r * 128 + c8 * 2);
        *(uint4*)(smem + AOFF_QHI + so) = H;
        *(uint4*)(smem + AOFF_QLO + so) = L;
    }
    __syncthreads();
    uint32_t tmem;
    asm volatile("ld.shared.b32 %0, [%1];" : "=r"(tmem) : "r"(sb + 0));

    const float* biasTile = bias + ((size_t)h * Tn + qt * 128) * Tn;
    float rowsum = 0.f;

    for (int kt = 0; kt < 16; ++kt) {
        if (kt > 0) mbar_wait(sb + 16, (kt - 1) & 1);   // PV(kt-1) done: K/P/Vt free
        // ---- fill K (64x64, hi/lo) ----
        const float* Kbase = g_K + ((size_t)bh * Tn + kt * 64) * HDn;
        const float* Vbase = g_V + ((size_t)bh * Tn + kt * 64) * HDn;
#pragma unroll
        for (int t = 0; t < 2; ++t) {
            const int s = tid + t * 256;        // 0..511
            const int r = s >> 3, c8 = (s & 7) << 3;
            const float* src = Kbase + (size_t)r * HDn + c8;
            uint4 H, L;
            split_pack8(*(const float4*)src, *(const float4*)(src + 4), H, L);
            const uint32_t so = SWZ(r * 128 + c8 * 2);
            *(uint4*)(smem + AOFF_KHI + so) = H;
            *(uint4*)(smem + AOFF_KLO + so) = L;
        }
        // ---- fill Vt (transposed 64d x 64keys, paired-key 4B stores) ----
#pragma unroll
        for (int it = 0; it < 2; ++it) {
            const int u = tid + it * 256;       // 0..511
            const int kp = u & 31;              // key pair -> keys 2kp, 2kp+1
            const int dg = u >> 5;              // 0..15 -> d = dg*4..dg*4+3
            const int key0 = kp * 2;
            const float4 va = *(const float4*)(Vbase + (size_t)key0 * HDn + dg * 4);
            const float4 vb = *(const float4*)(Vbase + (size_t)(key0 + 1) * HDn + dg * 4);
            const float fa[4] = {va.x, va.y, va.z, va.w};
            const float fb[4] = {vb.x, vb.y, vb.z, vb.w};
#pragma unroll
            for (int dd = 0; dd < 4; ++dd) {
                const int d = dg * 4 + dd;
                const __nv_bfloat16 ha = __float2bfloat16(fa[dd]);
                const __nv_bfloat16 hb = __float2bfloat16(fb[dd]);
                const __nv_bfloat16 la = __float2bfloat16(fa[dd] - __bfloat162float(ha));
                const __nv_bfloat16 lb = __float2bfloat16(fb[dd] - __bfloat162float(hb));
                const uint32_t so = SWZ((uint32_t)(d * 128 + key0 * 2));
                *(uint32_t*)(smem + AOFF_VTHI + so) = pack2(ha, hb);
                *(uint32_t*)(smem + AOFF_VTLO + so) = pack2(la, lb);
            }
        }
        if (tid < 64)
            mk[tid] = (mask[b * Tn + kt * 64 + tid] != 0u) ? NEG_INF : 0.f;
        __syncthreads();

        // ---- S = QK^T (3-term split), into TMEM cols 0-63 ----
        if (wid == 0 && elect1()) {
            asm volatile("fence.proxy.async.shared::cta;" ::: "memory");
            const uint64_t dQh = make_desc(sb + AOFF_QHI);
            const uint64_t dQl = make_desc(sb + AOFF_QLO);
            const uint64_t dKh = make_desc(sb + AOFF_KHI);
            const uint64_t dKl = make_desc(sb + AOFF_KLO);
#pragma unroll
            for (int ks = 0; ks < 4; ++ks)
                mma_f16_ss(tmem, dQh + ks * 2, dKh + ks * 2, IDESC_N64, ks > 0 ? 1u : 0u);
#pragma unroll
            for (int ks = 0; ks < 4; ++ks)
                mma_f16_ss(tmem, dQh + ks * 2, dKl + ks * 2, IDESC_N64, 1u);
#pragma unroll
            for (int ks = 0; ks < 4; ++ks)
                mma_f16_ss(tmem, dQl + ks * 2, dKh + ks * 2, IDESC_N64, 1u);
            tc_commit(sb + 8);
        }

        // ---- stage bias+mask tile into SMEM as bf16 (overlaps S MMA) ----
        // layout: 32 words/row (128B), word w stored at w ^ (row & 31)
        {
            const float* bsrc = biasTile + kt * 64;
#pragma unroll
            for (int t = 0; t < 8; ++t) {
                const int f = tid + t * 256;        // 0..2047
                const int r = f >> 4;               // 0..127
                const int cq = (f & 15) * 4;        // 0..60
                float4 v = *(const float4*)(bsrc + (size_t)r * Tn + cq);
                v.x += mk[cq];     v.y += mk[cq + 1];
                v.z += mk[cq + 2]; v.w += mk[cq + 3];
                const uint32_t w0 = pack2(__float2bfloat16(v.x), __float2bfloat16(v.y));
                const uint32_t w1 = pack2(__float2bfloat16(v.z), __float2bfloat16(v.w));
                uint32_t* bs = (uint32_t*)(smem + AOFF_BIAS + r * 128);
                const int wb = cq >> 1;
                bs[wb ^ (r & 31)]       = w0;
                bs[(wb + 1) ^ (r & 31)] = w1;
            }
        }
        __syncthreads();

        mbar_wait(sb + 8, kt & 1);   // S done: K region free -> P-hi writable
        tc_fence_after();

        // ---- softmax numerator: p = exp(S + bias_s); split to bf16 ----
        {
            const uint32_t* brow = (const uint32_t*)(smem + AOFF_BIAS + row * 128);
            uint32_t r[32];
            ldtm_x32(r, tmem + half * 32);
            tc_wait_ld();
            const int c0 = half * 32;
#pragma unroll
            for (int j = 0; j < 32; j += 2) {
                const uint32_t bw = brow[((c0 + j) >> 1) ^ (row & 31)];
                const __nv_bfloat162 bb = *reinterpret_cast<const __nv_bfloat162*>(&bw);
                const float s0 = __uint_as_float(r[j])     + __bfloat162float(bb.x);
                const float s1 = __uint_as_float(r[j + 1]) + __bfloat162float(bb.y);
                const float p0 = __expf(s0);
                const float p1 = __expf(s1);
                rowsum += p0 + p1;
                const __nv_bfloat16 h0 = __float2bfloat16(p0);
                const __nv_bfloat16 h1 = __float2bfloat16(p1);
                const __nv_bfloat16 l0 = __float2bfloat16(p0 - __bfloat162float(h0));
                const __nv_bfloat16 l1 = __float2bfloat16(p1 - __bfloat162float(h1));
                const uint32_t so = SWZ((uint32_t)(row * 128 + (c0 + j) * 2));
                *(uint32_t*)(smem + AOFF_PHI + so) = pack2(h0, h1);
                *(uint32_t*)(smem + AOFF_PLO + so) = pack2(l0, l1);
            }
        }
        __syncthreads();

        // ---- O += P V (3-term split), into TMEM cols 64-127 ----
        if (wid == 0 && elect1()) {
            asm volatile("fence.proxy.async.shared::cta;" ::: "memory");
            const uint64_t dPh = make_desc(sb + AOFF_PHI);
            const uint64_t dPl = make_desc(sb + AOFF_PLO);
            const uint64_t dVh = make_desc(sb + AOFF_VTHI);
            const uint64_t dVl = make_desc(sb + AOFF_VTLO);
#pragma unroll
            for (int ks = 0; ks < 4; ++ks)
                mma_f16_ss(tmem + 64, dPh + ks * 2, dVh + ks * 2, IDESC_N64,
                           (kt == 0 && ks == 0) ? 0u : 1u);
#pragma unroll
            for (int ks = 0; ks < 4; ++ks)
                mma_f16_ss(tmem + 64, dPh + ks * 2, dVl + ks * 2, IDESC_N64, 1u);
#pragma unroll
            for (int ks = 0; ks < 4; ++ks)
                mma_f16_ss(tmem + 64, dPl + ks * 2, dVh + ks * 2, IDESC_N64, 1u);
            tc_commit(sb + 16);
        }
    }
    mbar_wait(sb + 16, 15 & 1);
    tc_fence_after();

    // ---- epilogue: rowsum combine, O/rowsum, fused hi/lo split -> g_Ahi/lo --
    rs[half * 128 + row] = rowsum;
    __syncthreads();
    const float inv = 1.f / (rs[row] + rs[128 + row]);
    {
        uint32_t r[32];
        ldtm_x32(r, tmem + 64 + half * 32);
        tc_wait_ld();
        tc_fence_before();
        const int q_global = qt * 128 + row;
        const size_t base = ((size_t)q_global * Bn + b) * En + h * HDn + half * 32;
#pragma unroll
        for (int j = 0; j < 8; ++j) {
            float f[4];
            f[0] = __uint_as_float(r[j * 4 + 0]) * inv;
            f[1] = __uint_as_float(r[j * 4 + 1]) * inv;
            f[2] = __uint_as_float(r[j * 4 + 2]) * inv;
            f[3] = __uint_as_float(r[j * 4 + 3]) * inv;
            uint2 hv, lv;
#pragma unroll
            for (int i = 0; i < 2; ++i) {
                const __nv_bfloat16 h0 = __float2bfloat16(f[2 * i]);
                const __nv_bfloat16 h1 = __float2bfloat16(f[2 * i + 1]);
                ((uint32_t*)&hv)[i] = pack2(h0, h1);
                ((uint32_t*)&lv)[i] = pack2(
                    __float2bfloat16(f[2 * i]     - __bfloat162float(h0)),
                    __float2bfloat16(f[2 * i + 1] - __bfloat162float(h1)));
            }
            *(uint2*)(g_Ahi + base + j * 4) = hv;
            *(uint2*)(g_Alo + base + j * 4) = lv;
        }
    }
    __syncthreads();
    if (wid == 0) {
        if (elect1()) { mbar_inval(sb + 8); mbar_inval(sb + 16); }
        tmem_dealloc(tmem, 128);
    }
#else
    // FFMA fallback (never selected on sm_103a). One thread per q row.
    if (tid < 128) {
        const int q = qt * 128 + tid;
        const float* Qr = g_Q + ((size_t)bh * Tn + q) * HDn;
        float qv[64];
#pragma unroll
        for (int d = 0; d < 64; ++d) qv[d] = Qr[d];
        float o[64];
#pragma unroll
        for (int d = 0; d < 64; ++d) o[d] = 0.f;
        float sum = 0.f;
        const float* bp = bias + ((size_t)h * Tn + q) * Tn;
        for (int key = 0; key < Tn; ++key) {
            float s = bp[key];
            if (mask[b * Tn + key] != 0u) continue;
            const float* Kr = g_K + ((size_t)bh * Tn + key) * HDn;
            for (int d = 0; d < 64; ++d) s = fmaf(qv[d], Kr[d], s);
            const float p = __expf(s);
            sum += p;
            const float* Vr = g_V + ((size_t)bh * Tn + key) * HDn;
            for (int d = 0; d < 64; ++d) o[d] = fmaf(p, Vr[d], o[d]);
        }
        const float inv = 1.f / sum;
        const size_t base = ((size_t)q * Bn + b) * En + h * HDn;
        for (int d = 0; d < 64; ++d) {
            const float v = o[d] * inv;
            const __nv_bfloat16 hi = __float2bfloat16(v);
            g_Ahi[base + d] = hi;
            g_Alo[base + d] = __float2bfloat16(v - __bfloat162float(hi));
        }
    }
#endif
}

// ---------------------------------------------------------------------------
extern "C" void kernel_launch(void* const* d_in, const int* in_sizes, int n_in,
                              void* d_out, int out_size)
{
    (void)in_sizes; (void)n_in; (void)out_size;
    const float*        query = (const float*)d_in[0];
    const unsigned int* mask  = (const unsigned int*)d_in[1];
    const float*        bias  = (const float*)d_in[2];
    const float*        wq    = (const float*)d_in[3];
    const float*        wk    = (const float*)d_in[4];
    const float*        wv    = (const float*)d_in[5];
    const float*        wo    = (const float*)d_in[6];
    float*              out   = (float*)d_out;

    cudaFuncSetAttribute(bgemm, cudaFuncAttributeMaxDynamicSharedMemorySize, BGEMM_SMEM);
    cudaFuncSetAttribute(tc_attn, cudaFuncAttributeMaxDynamicSharedMemorySize, ATT_SMEM);

    // split inputs + weights
    convert_split<<<(Mn * En / 4) / 256, 256>>>(query);
    convert_w<<<dim3(32, 32, 4), 256>>>(wq, wk, wv, wo);

    // QKV projections (tensor cores; 2 CTAs/SM; 128x256 tiles)
    bgemm<<<dim3(4, 64, 3), 256, BGEMM_SMEM>>>(0, nullptr);

    // attention (tensor cores; 2 CTAs/SM; writes split output directly)
    tc_attn<<<dim3(8, 128), 256, ATT_SMEM>>>(bias, mask);

    // output projection
    bgemm<<<dim3(4, 64, 1), 256, BGEMM_SMEM>>>(1, out);
}